// round 2
// baseline (speedup 1.0000x reference)
#include <cuda_runtime.h>

// Shape (fixed)
#define BB 4
#define MM 128
#define LL 512
#define DD 768

#define NEGV   (-1e30f)
#define LSPLIT 6          // L split across blocks -> grid 6*6*4 = 144 blocks
#define PAD    132        // padded m-row stride in sh_a (conflict-free: bank = (4l+m)&31)

// partial results [LSPLIT][B][M][D] = 9.4 MB static device scratch (no allocs)
__device__ float g_scratch[LSPLIT * BB * MM * DD];

__global__ __launch_bounds__(256, 1)
void mr_main(const float* __restrict__ h, const int* __restrict__ mask)
{
    __shared__ float sh_a[87 * PAD];   // [l][m] additive mask (0 or -1e30), l<=86

    const int b  = blockIdx.z;
    const int d0 = blockIdx.x * 128;
    const int sp = blockIdx.y;
    const int l0   = sp * 85 + (sp < 2 ? sp : 2);   // 86,86,85,85,85,85
    const int llen = 85 + (sp < 2 ? 1 : 0);

    const int tid  = threadIdx.x;
    const int lane = tid & 31;
    const int w    = tid >> 5;         // warp id: handles m in [w*16, w*16+16)

    // ---- stage additive mask, transposed to [l][m] ----
    // warp handles m = w, w+8, ... ; lanes cover consecutive l (coalesced LDG)
    for (int m = w; m < MM; m += 8) {
        const int* mrow = mask + ((size_t)b * MM + m) * LL + l0;
        for (int lb = lane; lb < llen; lb += 32)
            sh_a[lb * PAD + m] = mrow[lb] ? 0.0f : NEGV;
    }
    __syncthreads();

    // ---- accumulate: 16 m x 128 d per warp, regs-resident ----
    float4 acc[16];
#pragma unroll
    for (int i = 0; i < 16; ++i)
        acc[i] = make_float4(NEGV, NEGV, NEGV, NEGV);

    const float4* hp = (const float4*)(h + ((size_t)b * LL + l0) * DD + d0) + lane;
    const float*  ab = sh_a + w * 16;

    for (int l = 0; l < llen; ++l) {
        const float4 hv = hp[(size_t)l * (DD / 4)];
        const float4* ap = (const float4*)(ab + l * PAD);
        float a[16];
#pragma unroll
        for (int k = 0; k < 4; ++k) {
            const float4 t = ap[k];    // uniform address -> broadcast
            a[4*k+0] = t.x; a[4*k+1] = t.y; a[4*k+2] = t.z; a[4*k+3] = t.w;
        }
#pragma unroll
        for (int i = 0; i < 16; ++i) {
            acc[i].x = fmaxf(acc[i].x, hv.x + a[i]);
            acc[i].y = fmaxf(acc[i].y, hv.y + a[i]);
            acc[i].z = fmaxf(acc[i].z, hv.z + a[i]);
            acc[i].w = fmaxf(acc[i].w, hv.w + a[i]);
        }
    }

    // ---- write partials [sp][b][m][d], coalesced float4 ----
    float* outp = g_scratch + (((size_t)sp * BB + b) * MM + w * 16) * DD + d0 + lane * 4;
#pragma unroll
    for (int i = 0; i < 16; ++i)
        *(float4*)(outp + (size_t)i * DD) = acc[i];
}

__global__ __launch_bounds__(256, 1)
void mr_combine(float* __restrict__ out)
{
    const int i4 = blockIdx.x * 256 + threadIdx.x;     // 0 .. 98303 (B*M*D/4)
    const float4* s = (const float4*)g_scratch;
    float4 r = s[i4];
#pragma unroll
    for (int sp = 1; sp < LSPLIT; ++sp) {
        const float4 t = s[(size_t)sp * (BB * MM * DD / 4) + i4];
        r.x = fmaxf(r.x, t.x);
        r.y = fmaxf(r.y, t.y);
        r.z = fmaxf(r.z, t.z);
        r.w = fmaxf(r.w, t.w);
    }
    ((float4*)out)[i4] = r;
}

extern "C" void kernel_launch(void* const* d_in, const int* in_sizes, int n_in,
                              void* d_out, int out_size)
{
    const float* h    = (const float*)d_in[0];
    const int*   mask = (const int*)  d_in[1];
    float*       out  = (float*)d_out;

    dim3 grid(DD / 128, LSPLIT, BB);   // 6 x 6 x 4 = 144 blocks
    mr_main<<<grid, 256>>>(h, mask);
    mr_combine<<<(BB * MM * DD / 4) / 256, 256>>>(out);
}

// round 3
// speedup vs baseline: 1.5283x; 1.5283x over previous
#include <cuda_runtime.h>

#define BB 4
#define MM 128
#define LL 512
#define DD 768

#define NEGV   (-1e30f)
#define LSPLIT 6
#define LMAX   86
#define RAWPAD 92          // raw mask row stride (bytes), odd/4 -> conflict-free ballot reads

// partial results [LSPLIT][B][M][D] = 9.4 MB static scratch (no allocs)
__device__ float g_scratch[LSPLIT * BB * MM * DD];

// smem layout (dynamic): h tile [LMAX][256] f32, raw mask [64][RAWPAD] u8, bits [LMAX] u64
#define SH_H_F4   (LMAX * 64)                 // float4 count
#define SH_RAW_OFF (LMAX * 256 * 4)           // byte offset
#define SH_BITS_OFF (SH_RAW_OFF + 64 * RAWPAD + 32)
#define SMEM_BYTES (SH_BITS_OFF + LMAX * 8 + 16)

__global__ __launch_bounds__(256, 1)
void mr_main(const float* __restrict__ h, const int* __restrict__ mask)
{
    extern __shared__ char smem[];
    float4*        sh_h    = (float4*)smem;                       // [l][64] float4
    unsigned char* sh_raw  = (unsigned char*)(smem + SH_RAW_OFF); // [m][RAWPAD]
    unsigned int*  sh_b32  = (unsigned int*) (smem + SH_BITS_OFF);// [l][2]
    unsigned char* sh_b8   = (unsigned char*)(smem + SH_BITS_OFF);// [l][8]

    const int b     = blockIdx.z;
    const int d0    = blockIdx.x * 256;
    const int sp    = blockIdx.y >> 1;
    const int m0    = (blockIdx.y & 1) * 64;
    const int l0    = sp * 85 + (sp < 2 ? sp : 2);
    const int llen  = 85 + (sp < 2 ? 1 : 0);

    const int tid  = threadIdx.x;
    const int lane = tid & 31;
    const int w    = tid >> 5;          // warp: m rows [m0 + w*8, m0 + w*8 + 8)

    // ---- stage h tile [llen][256] (coalesced float4) ----
    const int nf4 = llen * 64;
    for (int idx = tid; idx < nf4; idx += 256) {
        const int l = idx >> 6, q = idx & 63;
        sh_h[idx] = *(const float4*)(h + ((size_t)b * LL + l0 + l) * DD + d0 + q * 4);
    }
    // ---- stage raw mask bytes [m][l] (coalesced over l) ----
    for (int m = w; m < 64; m += 8) {
        const int* mr = mask + ((size_t)b * MM + m0 + m) * LL + l0;
        for (int lb = lane; lb < llen; lb += 32)
            sh_raw[m * RAWPAD + lb] = (unsigned char)mr[lb];
    }
    __syncthreads();
    // ---- pack to 64-bit per l via ballot ----
    for (int l = w; l < llen; l += 8) {
        const unsigned lo = __ballot_sync(~0u, sh_raw[lane * RAWPAD + l]);
        const unsigned hi = __ballot_sync(~0u, sh_raw[(32 + lane) * RAWPAD + l]);
        if (lane == 0) { sh_b32[l * 2] = lo; sh_b32[l * 2 + 1] = hi; }
    }
    __syncthreads();

    // ---- accumulate: 8 m x 256 d per warp, predicated max ----
    float acc[8][8];
#pragma unroll
    for (int i = 0; i < 8; ++i)
#pragma unroll
        for (int j = 0; j < 8; ++j)
            acc[i][j] = NEGV;

    for (int l = 0; l < llen; ++l) {
        const float4 h0 = sh_h[l * 64 + lane];
        const float4 h1 = sh_h[l * 64 + 32 + lane];
        const unsigned bitsv = sh_b8[l * 8 + w];
#pragma unroll
        for (int i = 0; i < 8; ++i) {
            const unsigned t = bitsv & (1u << i);
            asm("{\n\t"
                ".reg .pred p;\n\t"
                "setp.ne.u32 p, %8, 0;\n\t"
                "@p max.f32 %0, %0, %9;\n\t"
                "@p max.f32 %1, %1, %10;\n\t"
                "@p max.f32 %2, %2, %11;\n\t"
                "@p max.f32 %3, %3, %12;\n\t"
                "@p max.f32 %4, %4, %13;\n\t"
                "@p max.f32 %5, %5, %14;\n\t"
                "@p max.f32 %6, %6, %15;\n\t"
                "@p max.f32 %7, %7, %16;\n\t"
                "}"
                : "+f"(acc[i][0]), "+f"(acc[i][1]), "+f"(acc[i][2]), "+f"(acc[i][3]),
                  "+f"(acc[i][4]), "+f"(acc[i][5]), "+f"(acc[i][6]), "+f"(acc[i][7])
                : "r"(t),
                  "f"(h0.x), "f"(h0.y), "f"(h0.z), "f"(h0.w),
                  "f"(h1.x), "f"(h1.y), "f"(h1.z), "f"(h1.w));
        }
    }

    // ---- write partials [sp][b][m][d] (coalesced float4) ----
    float* op = g_scratch + (((size_t)sp * BB + b) * MM + m0 + w * 8) * DD + d0;
#pragma unroll
    for (int i = 0; i < 8; ++i) {
        float4 o0, o1;
        o0.x = acc[i][0]; o0.y = acc[i][1]; o0.z = acc[i][2]; o0.w = acc[i][3];
        o1.x = acc[i][4]; o1.y = acc[i][5]; o1.z = acc[i][6]; o1.w = acc[i][7];
        *(float4*)(op + (size_t)i * DD + lane * 4)       = o0;
        *(float4*)(op + (size_t)i * DD + 128 + lane * 4) = o1;
    }
}

#define TOT4 (BB * MM * DD / 4)     // 98304 float4
#define HALF4 (TOT4 / 2)            // 49152

__global__ __launch_bounds__(256, 1)
void mr_combine(float* __restrict__ out)
{
    const int t = blockIdx.x * 256 + threadIdx.x;      // 0..49151
    const float4* s = (const float4*)g_scratch;
    float4 r0 = s[t];
    float4 r1 = s[t + HALF4];
#pragma unroll
    for (int sp = 1; sp < LSPLIT; ++sp) {
        const float4 a = s[(size_t)sp * TOT4 + t];
        const float4 c = s[(size_t)sp * TOT4 + t + HALF4];
        r0.x = fmaxf(r0.x, a.x); r0.y = fmaxf(r0.y, a.y);
        r0.z = fmaxf(r0.z, a.z); r0.w = fmaxf(r0.w, a.w);
        r1.x = fmaxf(r1.x, c.x); r1.y = fmaxf(r1.y, c.y);
        r1.z = fmaxf(r1.z, c.z); r1.w = fmaxf(r1.w, c.w);
    }
    ((float4*)out)[t]         = r0;
    ((float4*)out)[t + HALF4] = r1;
}

extern "C" void kernel_launch(void* const* d_in, const int* in_sizes, int n_in,
                              void* d_out, int out_size)
{
    const float* h    = (const float*)d_in[0];
    const int*   mask = (const int*)  d_in[1];
    float*       out  = (float*)d_out;

    cudaFuncSetAttribute(mr_main,
                         cudaFuncAttributeMaxDynamicSharedMemorySize, SMEM_BYTES);

    dim3 grid(DD / 256, LSPLIT * 2, BB);   // 3 x 12 x 4 = 144 blocks
    mr_main<<<grid, 256, SMEM_BYTES>>>(h, mask);
    mr_combine<<<HALF4 / 256, 256>>>(out);  // 192 blocks
}